// round 2
// baseline (speedup 1.0000x reference)
#include <cuda_runtime.h>
#include <math.h>

#define NE 100000
#define NR 400
#define DI 200
#define DO 400
#define NEDGE 600000
#define HALFE 300000
#define NB 1024
#define NGROUP 800
#define BN_EPS 1e-5f

// ---------------- device scratch (no cudaMalloc allowed) ----------------
__device__ float g_M[(size_t)NGROUP * DI * DO];   // 256 MB fused ccorr+W per (half,rel)
__device__ float g_Mloop[DI * DO];
__device__ float g_x[(size_t)NE * DO];
__device__ float g_stats[2 * DO];
__device__ float g_scale[DO];
__device__ float g_shift[DO];
__device__ float g_r[NR * DO];
__device__ float g_obj[NB * DO];
__device__ int   g_hist[NGROUP];
__device__ int   g_off[NGROUP + 1];
__device__ int   g_pos[NGROUP];
__device__ int   g_eidx[NEDGE];

__device__ __forceinline__ void red4(float* p, float a, float b, float c, float d) {
    asm volatile("red.global.add.v4.f32 [%0], {%1,%2,%3,%4};"
                 :: "l"(p), "f"(a), "f"(b), "f"(c), "f"(d) : "memory");
}

// ---------------- zero scratch ----------------
__global__ void k_zero() {
    const size_t n4 = (size_t)NE * DO / 4;
    float4* p = reinterpret_cast<float4*>(g_x);
    const float4 z = make_float4(0.f, 0.f, 0.f, 0.f);
    for (size_t i = (size_t)blockIdx.x * blockDim.x + threadIdx.x; i < n4;
         i += (size_t)gridDim.x * blockDim.x)
        p[i] = z;
    int gid = blockIdx.x * blockDim.x + threadIdx.x;
    if (gid < NGROUP) g_hist[gid] = 0;
    if (gid < 2 * DO) g_stats[gid] = 0.f;
}

// ---------------- edge grouping ----------------
__global__ void k_hist(const int* __restrict__ et) {
    int e = blockIdx.x * blockDim.x + threadIdx.x;
    if (e < NEDGE) atomicAdd(&g_hist[et[e] + (e < HALFE ? 0 : 400)], 1);
}

__global__ void k_scan() {
    __shared__ int s[NGROUP];
    int i = threadIdx.x;
    if (i < NGROUP) s[i] = g_hist[i];
    __syncthreads();
    for (int d = 1; d < NGROUP; d <<= 1) {
        int v = 0;
        if (i < NGROUP && i >= d) v = s[i - d];
        __syncthreads();
        if (i < NGROUP && i >= d) s[i] += v;
        __syncthreads();
    }
    if (i < NGROUP) {
        int excl = s[i] - g_hist[i];
        g_off[i] = excl;
        g_pos[i] = excl;
        if (i == NGROUP - 1) g_off[NGROUP] = s[i];
    }
}

__global__ void k_scatter(const int* __restrict__ et) {
    int e = blockIdx.x * blockDim.x + threadIdx.x;
    if (e < NEDGE) {
        int p = atomicAdd(&g_pos[et[e] + (e < HALFE ? 0 : 400)], 1);
        g_eidx[p] = e;
    }
}

// ---------------- M precompute: M[t,o] = (1/3) sum_j b[(t+j)%200] W[j,o] ----------------
__global__ void k_M(const float* __restrict__ rel_emb, const float* __restrict__ in_w,
                    const float* __restrict__ out_w, const float* __restrict__ loop_w,
                    const float* __restrict__ loop_rel) {
    __shared__ float bb[464];
    int m = blockIdx.y;
    const float* bsrc;
    const float* W;
    float* outp;
    if (m < 800) {
        int h = m / 400, r = m - h * 400;
        bsrc = rel_emb + (size_t)r * DI;
        W = h ? out_w : in_w;
        outp = g_M + (size_t)m * (DI * DO);
    } else {
        bsrc = loop_rel;
        W = loop_w;
        outp = g_Mloop;
    }
    int tid = threadIdx.x;
    for (int s = tid; s < 464; s += 256) bb[s] = bsrc[s % DI];
    __syncthreads();

    int te = tid >> 4, to = tid & 15;
    int t0 = blockIdx.x * 64 + te * 4;
    const float S = 1.f / 3.f;

    for (int ot = 0; ot < 7; ++ot) {
        int n0 = ot * 64 + to * 4;
        if (n0 >= DO) continue;
        float acc[4][4] = {};
        for (int k = 0; k < DI; k += 4) {
            float aa[4][4], bv[4][4];
#pragma unroll
            for (int i = 0; i < 4; i++)
#pragma unroll
                for (int kk = 0; kk < 4; kk++)
                    aa[i][kk] = bb[t0 + i + k + kk];
#pragma unroll
            for (int kk = 0; kk < 4; kk++) {
                float4 t = *(const float4*)&W[(size_t)(k + kk) * DO + n0];
                bv[kk][0] = t.x; bv[kk][1] = t.y; bv[kk][2] = t.z; bv[kk][3] = t.w;
            }
#pragma unroll
            for (int i = 0; i < 4; i++)
#pragma unroll
                for (int j = 0; j < 4; j++)
#pragma unroll
                    for (int kk = 0; kk < 4; kk++)
                        acc[i][j] = fmaf(aa[i][kk], bv[kk][j], acc[i][j]);
        }
#pragma unroll
        for (int i = 0; i < 4; i++) {
            int row = t0 + i;
            if (row < DI)
                *(float4*)&outp[(size_t)row * DO + n0] =
                    make_float4(acc[i][0] * S, acc[i][1] * S, acc[i][2] * S, acc[i][3] * S);
        }
    }
}

// ---------------- edge messages + scatter-add ----------------
__global__ void k_edge(const float* __restrict__ ent_emb, const int* __restrict__ src,
                       const int* __restrict__ dst, const float* __restrict__ nrm) {
    extern __shared__ float xs[];  // [64][200], norm folded in
    __shared__ int s_dst[64];
    int g = blockIdx.y;
    int base = g_off[g];
    int ng = g_off[g + 1] - base;
    int tid = threadIdx.x;
    const float* B = g_M + (size_t)g * (DI * DO);
    int te = tid >> 4, to = tid & 15;
    int m0 = te * 4;

    for (int t0 = blockIdx.x * 64; t0 < ng; t0 += gridDim.x * 64) {
        int cnt = min(64, ng - t0);
        __syncthreads();
        if (tid < 64) {
            if (tid < cnt) {
                int e = g_eidx[base + t0 + tid];
                int sv = src[e];
                float nv = nrm[e];
                s_dst[tid] = dst[e];
                for (int k2 = 0; k2 < DI; k2++)
                    xs[tid * DI + k2] = ent_emb[(size_t)sv * DI + k2] * nv;
            } else {
                s_dst[tid] = 0;
                for (int k2 = 0; k2 < DI; k2++) xs[tid * DI + k2] = 0.f;
            }
        }
        __syncthreads();

        for (int ot = 0; ot < 7; ++ot) {
            int n0 = ot * 64 + to * 4;
            if (n0 >= DO) continue;
            float acc[4][4] = {};
            for (int k = 0; k < DI; k += 4) {
                float aa[4][4], bv[4][4];
#pragma unroll
                for (int i = 0; i < 4; i++) {
                    float4 t = *(const float4*)&xs[(m0 + i) * DI + k];
                    aa[i][0] = t.x; aa[i][1] = t.y; aa[i][2] = t.z; aa[i][3] = t.w;
                }
#pragma unroll
                for (int kk = 0; kk < 4; kk++) {
                    float4 t = *(const float4*)&B[(size_t)(k + kk) * DO + n0];
                    bv[kk][0] = t.x; bv[kk][1] = t.y; bv[kk][2] = t.z; bv[kk][3] = t.w;
                }
#pragma unroll
                for (int i = 0; i < 4; i++)
#pragma unroll
                    for (int j = 0; j < 4; j++)
#pragma unroll
                        for (int kk = 0; kk < 4; kk++)
                            acc[i][j] = fmaf(aa[i][kk], bv[kk][j], acc[i][j]);
            }
#pragma unroll
            for (int i = 0; i < 4; i++) {
                int mm = m0 + i;
                if (mm < cnt)
                    red4(g_x + (size_t)s_dst[mm] * DO + n0,
                         acc[i][0], acc[i][1], acc[i][2], acc[i][3]);
            }
        }
    }
}

// ---------------- self-loop GEMM + x finalize ----------------
__global__ void k_loopx(const float* __restrict__ ent_emb, const float* __restrict__ bias_w) {
    extern __shared__ float xs[];
    int row0 = blockIdx.x * 64;
    int cnt = min(64, NE - row0);
    int tid = threadIdx.x;

    for (int idx = tid; idx < cnt * DI; idx += 256) xs[idx] = ent_emb[(size_t)row0 * DI + idx];
    for (int idx = cnt * DI + tid; idx < 64 * DI; idx += 256) xs[idx] = 0.f;
    __syncthreads();

    int te = tid >> 4, to = tid & 15;
    int m0 = te * 4;

    for (int ot = 0; ot < 7; ++ot) {
        int n0 = ot * 64 + to * 4;
        if (n0 >= DO) continue;
        float acc[4][4] = {};
        for (int k = 0; k < DI; k += 4) {
            float aa[4][4], bv[4][4];
#pragma unroll
            for (int i = 0; i < 4; i++) {
                float4 t = *(const float4*)&xs[(m0 + i) * DI + k];
                aa[i][0] = t.x; aa[i][1] = t.y; aa[i][2] = t.z; aa[i][3] = t.w;
            }
#pragma unroll
            for (int kk = 0; kk < 4; kk++) {
                float4 t = *(const float4*)&g_Mloop[(size_t)(k + kk) * DO + n0];
                bv[kk][0] = t.x; bv[kk][1] = t.y; bv[kk][2] = t.z; bv[kk][3] = t.w;
            }
#pragma unroll
            for (int i = 0; i < 4; i++)
#pragma unroll
                for (int j = 0; j < 4; j++)
#pragma unroll
                    for (int kk = 0; kk < 4; kk++)
                        acc[i][j] = fmaf(aa[i][kk], bv[kk][j], acc[i][j]);
        }
        float4 b4 = *(const float4*)&bias_w[n0];
#pragma unroll
        for (int i = 0; i < 4; i++) {
            int mm = m0 + i;
            if (mm < cnt) {
                float* xr = g_x + (size_t)(row0 + mm) * DO + n0;
                float4 cur = *(float4*)xr;
                *(float4*)xr = make_float4(cur.x + acc[i][0] + b4.x, cur.y + acc[i][1] + b4.y,
                                           cur.z + acc[i][2] + b4.z, cur.w + acc[i][3] + b4.w);
            }
        }
    }
}

// ---------------- BN column stats ----------------
__global__ void k_stats() {
    int c = threadIdx.x;  // blockDim = 400
    float s = 0.f, q = 0.f;
    for (int r = blockIdx.x; r < NE; r += gridDim.x) {
        float v = g_x[(size_t)r * DO + c];
        s += v;
        q += v * v;
    }
    atomicAdd(&g_stats[c], s);
    atomicAdd(&g_stats[DO + c], q);
}

__global__ void k_bn(const float* __restrict__ gamma, const float* __restrict__ beta) {
    int c = threadIdx.x;
    if (c < DO) {
        float mean = g_stats[c] / (float)NE;
        float var = g_stats[DO + c] / (float)NE - mean * mean;
        float sc = gamma[c] * rsqrtf(var + BN_EPS);
        g_scale[c] = sc;
        g_shift[c] = beta[c] - mean * sc;
    }
}

// ---------------- r = rel_emb @ w_rel (tiny, naive) ----------------
__global__ void k_rel(const float* __restrict__ rel_emb, const float* __restrict__ w_rel) {
    int idx = blockIdx.x * blockDim.x + threadIdx.x;
    if (idx < NR * DO) {
        int row = idx / DO, col = idx - row * DO;
        float acc = 0.f;
        for (int k = 0; k < DI; k++)
            acc = fmaf(rel_emb[row * DI + k], w_rel[k * DO + col], acc);
        g_r[idx] = acc;
    }
}

// ---------------- obj = tanh(bn(x[head])) * r[rel] ----------------
__global__ void k_obj(const int* __restrict__ triples) {
    int idx = blockIdx.x * blockDim.x + threadIdx.x;
    if (idx < NB * DO) {
        int i = idx / DO, c = idx - i * DO;
        int h = triples[3 * i], rl = triples[3 * i + 1];
        float v = tanhf(g_x[(size_t)h * DO + c] * g_scale[c] + g_shift[c]);
        g_obj[idx] = v * g_r[rl * DO + c];
    }
}

// ---------------- score = sigmoid(obj @ emb^T + bias), 1024 x 100000 ----------------
#define KC 80
#define KST 84
__global__ void k_score(const float* __restrict__ emb, const float* __restrict__ ebias,
                        float* __restrict__ out) {
    __shared__ float As[64 * KST];
    __shared__ float Bs[64 * KST];
    int i0 = blockIdx.x * 64;
    int e0 = blockIdx.y * 64;
    int tid = threadIdx.x;
    int te = tid >> 4, to = tid & 15;
    int m0 = te * 4, n0 = to * 4;
    float acc[4][4] = {};

    for (int kc = 0; kc < 5; ++kc) {
        int k0 = kc * KC;
        __syncthreads();
        for (int idx = tid; idx < 64 * (KC / 4); idx += 256) {
            int row = idx / (KC / 4), q = idx - row * (KC / 4);
            *(float4*)&As[row * KST + q * 4] =
                *(const float4*)&g_obj[(size_t)(i0 + row) * DO + k0 + q * 4];
            int e = e0 + row;
            float4 v = make_float4(0.f, 0.f, 0.f, 0.f);
            if (e < NE) v = *(const float4*)&emb[(size_t)e * DO + k0 + q * 4];
            *(float4*)&Bs[row * KST + q * 4] = v;
        }
        __syncthreads();
#pragma unroll 4
        for (int k = 0; k < KC; k += 4) {
            float aa[4][4], bb[4][4];
#pragma unroll
            for (int i = 0; i < 4; i++) {
                float4 t = *(const float4*)&As[(m0 + i) * KST + k];
                aa[i][0] = t.x; aa[i][1] = t.y; aa[i][2] = t.z; aa[i][3] = t.w;
            }
#pragma unroll
            for (int j = 0; j < 4; j++) {
                float4 t = *(const float4*)&Bs[(n0 + j) * KST + k];
                bb[j][0] = t.x; bb[j][1] = t.y; bb[j][2] = t.z; bb[j][3] = t.w;
            }
#pragma unroll
            for (int i = 0; i < 4; i++)
#pragma unroll
                for (int j = 0; j < 4; j++)
#pragma unroll
                    for (int kk = 0; kk < 4; kk++)
                        acc[i][j] = fmaf(aa[i][kk], bb[j][kk], acc[i][j]);
        }
    }

    bool full = (e0 + 64 <= NE);
#pragma unroll
    for (int i = 0; i < 4; i++) {
        int row = i0 + m0 + i;
        if (full) {
            float4 r4;
            float* rp = &r4.x;
#pragma unroll
            for (int j = 0; j < 4; j++) {
                float v = acc[i][j] + ebias[e0 + n0 + j];
                rp[j] = 1.f / (1.f + __expf(-v));
            }
            *(float4*)&out[(size_t)row * NE + e0 + n0] = r4;
        } else {
#pragma unroll
            for (int j = 0; j < 4; j++) {
                int e = e0 + n0 + j;
                if (e < NE) {
                    float v = acc[i][j] + ebias[e];
                    out[(size_t)row * NE + e] = 1.f / (1.f + __expf(-v));
                }
            }
        }
    }
}

// ---------------- launch ----------------
extern "C" void kernel_launch(void* const* d_in, const int* in_sizes, int n_in,
                              void* d_out, int out_size) {
    const float* ent_emb  = (const float*)d_in[0];
    const float* rel_emb  = (const float*)d_in[1];
    const float* in_w     = (const float*)d_in[2];
    const float* out_w    = (const float*)d_in[3];
    const float* loop_w   = (const float*)d_in[4];
    const float* w_rel    = (const float*)d_in[5];
    const float* loop_rel = (const float*)d_in[6];
    const float* bias_w   = (const float*)d_in[7];
    const float* bn_gamma = (const float*)d_in[8];
    const float* bn_beta  = (const float*)d_in[9];
    const float* emb_ent  = (const float*)d_in[10];
    const float* ent_bias = (const float*)d_in[11];
    const int*   src      = (const int*)d_in[12];
    const int*   dst      = (const int*)d_in[13];
    const int*   et       = (const int*)d_in[14];
    const float* enorm    = (const float*)d_in[15];
    const int*   triples  = (const int*)d_in[16];
    float* out = (float*)d_out;

    const int SM_EDGE = 64 * DI * 4;  // 51200 > 48KB default
    cudaFuncSetAttribute(k_edge, cudaFuncAttributeMaxDynamicSharedMemorySize, SM_EDGE);
    cudaFuncSetAttribute(k_loopx, cudaFuncAttributeMaxDynamicSharedMemorySize, SM_EDGE);

    k_zero<<<4096, 256>>>();
    k_hist<<<(NEDGE + 255) / 256, 256>>>(et);
    k_scan<<<1, 1024>>>();
    k_scatter<<<(NEDGE + 255) / 256, 256>>>(et);
    k_M<<<dim3(4, 801), 256>>>(rel_emb, in_w, out_w, loop_w, loop_rel);
    k_edge<<<dim3(16, NGROUP), 256, SM_EDGE>>>(ent_emb, src, dst, enorm);
    k_loopx<<<(NE + 63) / 64, 256, SM_EDGE>>>(ent_emb, bias_w);
    k_stats<<<256, 400>>>();
    k_bn<<<1, 512>>>(bn_gamma, bn_beta);
    k_rel<<<(NR * DO + 255) / 256, 256>>>(rel_emb, w_rel);
    k_obj<<<(NB * DO + 255) / 256, 256>>>(triples);
    k_score<<<dim3(NB / 64, (NE + 63) / 64), 256>>>(emb_ent, ent_bias, out);
}